// round 1
// baseline (speedup 1.0000x reference)
#include <cuda_runtime.h>
#include <math.h>

// CroquetGNN: 2-layer GCN, N<=100000 nodes, E<=3200000 edges, feat 3 -> 16 -> 1
//
// out = sigmoid( GCNConv2( relu( GCNConv1(x) ) ) )
// GCNConv(x) restructured as:  dinv[d] * segsum_{s->d}( dinv[s]*x[s] )  @ W  (+ self loop + b)
// (aggregation commutes with the linear layer, norm factors split per endpoint)

#define MAXN 100000
#define MAXE 3200000
#define TB 256

// ---- scratch (static device globals; no allocation anywhere) ----
__device__ int    g_is64;          // 1 if edge_index is int64, 0 if int32
__device__ int2   g_edge[MAXE];    // converted (src,dst) int32 pairs
__device__ float  g_dinv[MAXN];    // deg count, then rsqrt(deg)
__device__ float4 g_xd[MAXN];      // dinv[i] * x[i]  (padded to float4)
__device__ float4 g_xagg[MAXN];    // layer-1 aggregation target
__device__ float  g_gd[MAXN];      // dinv[i] * (h1[i] . W2)
__device__ float  g_gagg[MAXN];    // layer-2 aggregation target

// ---- dtype detection: int64 little-endian with values < 2^31 has all-zero hi words ----
__global__ void k_detect(const int* __restrict__ idx) {
    if (threadIdx.x == 0 && blockIdx.x == 0) {
        int is64 = 1;
        for (int j = 0; j < 64; j++) {
            if (idx[2 * j + 1] != 0) { is64 = 0; break; }
        }
        g_is64 = is64;
    }
}

// ---- per-node scratch init: deg=1 (self-loop), aggs=0 ----
__global__ void k_zero(int n) {
    int i = blockIdx.x * blockDim.x + threadIdx.x;
    if (i < n) {
        g_dinv[i] = 1.0f;
        g_xagg[i] = make_float4(0.f, 0.f, 0.f, 0.f);
        g_gagg[i] = 0.f;
    }
}

// ---- convert edge dtype to int2 + count in-degree over dst ----
__global__ void k_convert_deg(const int* __restrict__ idx, int E) {
    int e = blockIdx.x * blockDim.x + threadIdx.x;
    if (e >= E) return;
    int s, d;
    if (g_is64) {
        const long long* p = (const long long*)idx;
        s = (int)p[e];
        d = (int)p[E + e];
    } else {
        s = idx[e];
        d = idx[E + e];
    }
    g_edge[e] = make_int2(s, d);
    atomicAdd(&g_dinv[d], 1.0f);
}

// ---- dinv = rsqrt(deg); xd = dinv * x (padded float4) ----
__global__ void k_xd(const float* __restrict__ x, int n) {
    int i = blockIdx.x * blockDim.x + threadIdx.x;
    if (i >= n) return;
    float di = rsqrtf(g_dinv[i]);   // deg >= 1 always (self loop)
    g_dinv[i] = di;
    g_xd[i] = make_float4(x[3 * i] * di, x[3 * i + 1] * di, x[3 * i + 2] * di, 0.f);
}

// ---- layer-1 edge aggregation: xagg[d] += xd[s]  (one v4 reduction per edge) ----
__global__ void k_edge1(int E) {
    int e = blockIdx.x * blockDim.x + threadIdx.x;
    if (e >= E) return;
    int2 ed = g_edge[e];
    float4 v = g_xd[ed.x];
    float* dst = (float*)&g_xagg[ed.y];
    asm volatile("red.global.add.v4.f32 [%0], {%1, %2, %3, %4};"
                 :: "l"(dst), "f"(v.x), "f"(v.y), "f"(v.z), "f"(v.w)
                 : "memory");
}

// ---- node epilogue 1: finish conv1 (+self loop, dinv[d], b1), relu, dot W2, scale dinv ----
__global__ void k_node1(const float* __restrict__ W1, const float* __restrict__ b1,
                        const float* __restrict__ W2, int n) {
    __shared__ float sW1[48], sb1[16], sW2[16];
    int t = threadIdx.x;
    if (t < 48) sW1[t] = W1[t];
    if (t < 16) { sb1[t] = b1[t]; sW2[t] = W2[t]; }
    __syncthreads();
    int i = blockIdx.x * blockDim.x + t;
    if (i >= n) return;
    float di = g_dinv[i];
    float4 a = g_xagg[i];
    float4 xd = g_xd[i];
    // self-loop contributes dinv[i]^2 * x[i] = dinv[i] * xd[i]
    float v0 = di * (a.x + xd.x);
    float v1 = di * (a.y + xd.y);
    float v2 = di * (a.z + xd.z);
    float g = 0.f;
#pragma unroll
    for (int c = 0; c < 16; c++) {
        float h = fmaf(v0, sW1[c], fmaf(v1, sW1[16 + c], fmaf(v2, sW1[32 + c], sb1[c])));
        h = fmaxf(h, 0.f);
        g = fmaf(h, sW2[c], g);
    }
    g_gd[i] = g * di;
}

// ---- layer-2 edge aggregation: gagg[d] += gd[s] ----
__global__ void k_edge2(int E) {
    int e = blockIdx.x * blockDim.x + threadIdx.x;
    if (e >= E) return;
    int2 ed = g_edge[e];
    atomicAdd(&g_gagg[ed.y], g_gd[ed.x]);
}

// ---- node epilogue 2: finish conv2 (+self loop, b2), sigmoid ----
__global__ void k_node2(const float* __restrict__ b2, float* __restrict__ out, int n) {
    int i = blockIdx.x * blockDim.x + threadIdx.x;
    if (i >= n) return;
    float di = g_dinv[i];
    float s = di * (g_gagg[i] + g_gd[i]) + b2[0];
    out[i] = 1.0f / (1.0f + expf(-s));
}

extern "C" void kernel_launch(void* const* d_in, const int* in_sizes, int n_in,
                              void* d_out, int out_size) {
    const float* x  = (const float*)d_in[0];
    const int*   idx = (const int*)d_in[1];   // int32 or int64 (detected on device)
    const float* W1 = (const float*)d_in[2];
    const float* b1 = (const float*)d_in[3];
    const float* W2 = (const float*)d_in[4];
    const float* b2 = (const float*)d_in[5];
    float* out = (float*)d_out;

    int N_ = in_sizes[0] / 3;   // 100000
    int E_ = in_sizes[1] / 2;   // 3200000

    int nb_n = (N_ + TB - 1) / TB;
    int nb_e = (E_ + TB - 1) / TB;

    k_detect<<<1, 32>>>(idx);
    k_zero<<<nb_n, TB>>>(N_);
    k_convert_deg<<<nb_e, TB>>>(idx, E_);
    k_xd<<<nb_n, TB>>>(x, N_);
    k_edge1<<<nb_e, TB>>>(E_);
    k_node1<<<nb_n, TB>>>(W1, b1, W2, N_);
    k_edge2<<<nb_e, TB>>>(E_);
    k_node2<<<nb_n, TB>>>(b2, out, N_);
}